// round 14
// baseline (speedup 1.0000x reference)
#include <cuda_runtime.h>
#include <stdint.h>
#include <math.h>

#define D_MODEL 1024
#define NHEAD   16
#define DH      64
#define SEQ     2048
#define BATCH   2
#define TOK     (BATCH * SEQ)              // 4096 tokens
#define OUT_ELEMS (TOK * D_MODEL)          // first output: [4096,1024]
// weights output: [2,16,2048,2048] floats follow OUT_ELEMS in d_out

// ---------------- scratch (device globals: allocation-free) ----------------
__device__ float g_q[BATCH * NHEAD * SEQ * DH];   // [b,h,s,dh]
__device__ float g_k[BATCH * NHEAD * SEQ * DH];
__device__ float g_v[BATCH * NHEAD * SEQ * DH];
__device__ float g_att[TOK * D_MODEL];            // attended, [token, d_model]
__device__ float g_li[BATCH * NHEAD * SEQ];       // 1/rowsum per (b,h,q)

// ---------------- helpers ----------------
__device__ __forceinline__ unsigned f2tf(float x) {
    unsigned u; asm("cvt.rna.tf32.f32 %0, %1;" : "=r"(u) : "f"(x)); return u;
}
__device__ __forceinline__ float ex2(float x) {
    float y; asm("ex2.approx.f32 %0, %1;" : "=f"(y) : "f"(x)); return y;
}
__device__ __forceinline__ void mma8(float c[4], const unsigned a[4],
                                     unsigned b0, unsigned b1) {
    asm volatile(
        "mma.sync.aligned.m16n8k8.row.col.f32.tf32.tf32.f32 "
        "{%0,%1,%2,%3}, {%4,%5,%6,%7}, {%8,%9}, {%0,%1,%2,%3};\n"
        : "+f"(c[0]), "+f"(c[1]), "+f"(c[2]), "+f"(c[3])
        : "r"(a[0]), "r"(a[1]), "r"(a[2]), "r"(a[3]), "r"(b0), "r"(b1));
}

// =====================================================================
// tf32 GEMM core (mma.sync): 128x128 block, BK=32, 256 thr = 8 warps,
// ping-pong smem, one __syncthreads per K-chunk.
// =====================================================================
#define GA 4096
#define GB 4608
#define G_SMEM (2 * (GA + GB) * 4) // 69,632 bytes

__device__ __forceinline__ void g_stage(unsigned* __restrict__ As,
                                        unsigned* __restrict__ Bs, int t,
                                        const float4* av, const float4* bv)
{
#pragma unroll
    for (int u = 0; u < 4; u++) {
        const int row = (t >> 3) + 32 * u, c4 = (t & 7) * 4;
        const int mt = row >> 4, r = row & 15;
        const float va[4] = {av[u].x, av[u].y, av[u].z, av[u].w};
#pragma unroll
        for (int e = 0; e < 4; e++) {
            const int col = c4 + e, ks = col >> 3, cc = col & 7;
            As[(((mt * 4 + ks) * 32 + ((r & 7) * 4 + (cc & 3))) << 2)
               + (r >> 3) + ((cc >> 2) << 1)] = f2tf(va[e]);
        }
        const int brow = (t >> 5) + 8 * u, bc4 = (t & 31) * 4;
        const int ksb = brow >> 3, kk = brow & 7;
        const float vb[4] = {bv[u].x, bv[u].y, bv[u].z, bv[u].w};
#pragma unroll
        for (int e = 0; e < 4; e++) {
            const int col = bc4 + e, nt = col >> 3, gg = col & 7;
            Bs[(ksb * 32 + gg * 4 + (kk & 3)) * 36
               + (nt >> 1) * 4 + (nt & 1) * 2 + (kk >> 2)] = f2tf(vb[e]);
        }
    }
}

__device__ __forceinline__ void g_compute(const unsigned* __restrict__ As,
                                          const unsigned* __restrict__ Bs,
                                          int wm, int wn, int lane,
                                          float acc[2][8][4])
{
#pragma unroll
    for (int ks = 0; ks < 4; ks++) {
        uint4 afr[2], bfr[4];
#pragma unroll
        for (int i = 0; i < 2; i++)
            afr[i] = *(const uint4*)&As[(((2 * wm + i) * 4 + ks) * 32 + lane) * 4];
#pragma unroll
        for (int j = 0; j < 4; j++)
            bfr[j] = *(const uint4*)&Bs[(ks * 32 + lane) * 36 + 16 * wn + 4 * j];
#pragma unroll
        for (int i = 0; i < 2; i++)
#pragma unroll
            for (int n = 0; n < 8; n++) {
                const unsigned* bp = (const unsigned*)&bfr[n >> 1];
                const unsigned b0 = (n & 1) ? bp[2] : bp[0];
                const unsigned b1 = (n & 1) ? bp[3] : bp[1];
                mma8(acc[i][n], (const unsigned*)&afr[i], b0, b1);
            }
    }
}

// Shared mainloop; epilogue differs by MODE.
template <int MODE>
__device__ __forceinline__ void gemm_body(const float* __restrict__ A,
                                          const float* __restrict__ B,
                                          const float* __restrict__ bias,
                                          float* __restrict__ C,
                                          unsigned* __restrict__ gsm)
{
    unsigned* As = gsm;
    unsigned* Bs = gsm + 2 * GA;

    const int t = threadIdx.x, lane = t & 31, w = t >> 5;
    const int wm = w >> 1, wn = w & 1;
    const int m0 = blockIdx.y * 128, n0 = blockIdx.x * 128;

    float acc[2][8][4];
#pragma unroll
    for (int i = 0; i < 2; i++)
#pragma unroll
        for (int n = 0; n < 8; n++)
#pragma unroll
            for (int e = 0; e < 4; e++) acc[i][n][e] = 0.f;

    const float* Ap = A + (size_t)(m0 + (t >> 3)) * D_MODEL + (t & 7) * 4;
    const float* Bp = B + (size_t)(t >> 5) * D_MODEL + n0 + (t & 31) * 4;

    float4 av[4], bv[4];
#pragma unroll
    for (int u = 0; u < 4; u++) {
        av[u] = *(const float4*)(Ap + (size_t)(32 * u) * D_MODEL);
        bv[u] = *(const float4*)(Bp + (size_t)(8 * u) * D_MODEL);
    }
    g_stage(As, Bs, t, av, bv);
    __syncthreads();

    for (int kb = 0; kb < 32; kb++) {
        const int cur = kb & 1;
        if (kb < 31) {
            const int k0 = (kb + 1) * 32;
#pragma unroll
            for (int u = 0; u < 4; u++) {
                av[u] = *(const float4*)(Ap + (size_t)(32 * u) * D_MODEL + k0);
                bv[u] = *(const float4*)(Bp + (size_t)(k0 + 8 * u) * D_MODEL);
            }
        }
        g_compute(As + cur * GA, Bs + cur * GB, wm, wn, lane, acc);
        if (kb < 31) {
            g_stage(As + (cur ^ 1) * GA, Bs + (cur ^ 1) * GB, t, av, bv);
            __syncthreads();
        }
    }

    const int g = lane >> 2, tq = lane & 3;
#pragma unroll
    for (int i = 0; i < 2; i++) {
        const int mrow = m0 + 32 * wm + 16 * i + g;
#pragma unroll
        for (int n = 0; n < 8; n++) {
            const int nc = n0 + 64 * wn + 8 * n + 2 * tq;
            const float2 bb = *(const float2*)(bias + nc);
            const float2 lo = make_float2(acc[i][n][0] + bb.x, acc[i][n][1] + bb.y);
            const float2 hi = make_float2(acc[i][n][2] + bb.x, acc[i][n][3] + bb.y);
            if (MODE == 0) {
                *(float2*)(C + (size_t)mrow * D_MODEL + nc) = lo;
                *(float2*)(C + (size_t)(mrow + 8) * D_MODEL + nc) = hi;
            } else {
                const int hh = nc >> 6, dh = nc & 63;
                const int b0i = mrow >> 11, s0 = mrow & (SEQ - 1);
                *(float2*)(C + ((size_t)(b0i * NHEAD + hh) * SEQ + s0) * DH + dh) = lo;
                const int m2 = mrow + 8;
                const int b1i = m2 >> 11, s1 = m2 & (SEQ - 1);
                *(float2*)(C + ((size_t)(b1i * NHEAD + hh) * SEQ + s1) * DH + dh) = hi;
            }
        }
    }
}

// fused Q/K/V projection: blockIdx.z selects weight/bias/output
__global__ __launch_bounds__(256, 1)
void gemm_qkv(const float* __restrict__ x,
              const float* __restrict__ wq, const float* __restrict__ wk,
              const float* __restrict__ wv,
              const float* __restrict__ bq, const float* __restrict__ bk,
              const float* __restrict__ bv,
              float* __restrict__ qp, float* __restrict__ kp,
              float* __restrict__ vp)
{
    extern __shared__ unsigned gsm[];
    const int z = blockIdx.z;
    const float* B  = (z == 0) ? wq : (z == 1) ? wk : wv;
    const float* bi = (z == 0) ? bq : (z == 1) ? bk : bv;
    float*       C  = (z == 0) ? qp : (z == 1) ? kp : vp;
    gemm_body<1>(x, B, bi, C, gsm);
}

__global__ __launch_bounds__(256, 1)
void gemm_out(const float* __restrict__ A, const float* __restrict__ B,
              const float* __restrict__ bias, float* __restrict__ C)
{
    extern __shared__ unsigned gsm[];
    gemm_body<0>(A, B, bias, C, gsm);
}

// =====================================================================
// SINGLE-PASS tf32 attention, 512 threads = 16 warps.
// S: warp grid 4m x 4n, warp tile 32x32.  PV: 4m x 4dh, warp tile 32x16.
// p = exp2(s') unnormalized; l in registers; O *= 1/l; W unnormalized
// (norm_w applies 1/l afterwards).
// =====================================================================
#define ATTN_SMEM (44544 * 4)   // 178,176 bytes

__global__ __launch_bounds__(512, 1)
void attn_tf32(float* __restrict__ W)
{
    extern __shared__ unsigned smr[];
    unsigned* Qs = smr;                 // [mt8][ks8][lane][4]      8192
    unsigned* Ks = smr + 8192;          // [ks8][lane][36]          9216
    unsigned* Vs = smr + 17408;         // [ks16][lane][20]        10240
    unsigned* Ps = smr + 27648;         // [mt8][ks16][lane][4]    16384
    float*    ls = (float*)(smr + 44032);                       //   512

    const int t = threadIdx.x, lane = t & 31, w = t >> 5;
    const int wm = w >> 2, wn = w & 3;
    const int g = lane >> 2, tq = lane & 3;
    const int qt = blockIdx.x, h = blockIdx.y, b = blockIdx.z;
    const int bh = b * NHEAD + h;
    const int q0 = qt * 128;

    const float* Qp = g_q + ((size_t)bh * SEQ + q0) * DH;
    const float* Kp = g_k + (size_t)bh * SEQ * DH;
    const float* Vp = g_v + (size_t)bh * SEQ * DH;

    // stage Q once, scaled by (1/8)*log2(e) so scores are exp2-ready
    const float qscale = 0.125f * 1.4426950408889634f;
#pragma unroll
    for (int u = 0; u < 4; u++) {
        const int f = t + 512 * u;
        const int row = f >> 4, d4 = (f & 15) * 4;
        const float4 qv = *(const float4*)(Qp + row * DH + d4);
        const int mt = row >> 4, r = row & 15;
        float vv[4] = {qv.x, qv.y, qv.z, qv.w};
#pragma unroll
        for (int e = 0; e < 4; e++) {
            const int col = d4 + e, ks = col >> 3, cc = col & 7;
            Qs[(((mt * 8 + ks) * 32 + ((r & 7) * 4 + (cc & 3))) << 2)
               + (r >> 3) + ((cc >> 2) << 1)] = f2tf(qscale * vv[e]);
        }
    }
    ls[t] = 0.f;
    __syncthreads();

    float oacc[2][2][4];
    float lr[2][2];                     // [i][half]: rows 16i+g, 16i+g+8
#pragma unroll
    for (int i = 0; i < 2; i++) {
        lr[i][0] = 0.f; lr[i][1] = 0.f;
#pragma unroll
        for (int n = 0; n < 2; n++)
#pragma unroll
            for (int e = 0; e < 4; e++) oacc[i][n][e] = 0.f;
    }

    for (int kt = 0; kt < 16; kt++) {
        // ---- stage K (B-frag order) and V (B-frag order, token as k) ----
#pragma unroll
        for (int u = 0; u < 4; u++) {
            const int f = t + 512 * u;
            const int tok = f >> 4, d4 = (f & 15) * 4;
            const float4 kv = *(const float4*)(Kp + (kt * 128 + tok) * DH + d4);
            const float4 vv = *(const float4*)(Vp + (kt * 128 + tok) * DH + d4);
            const int ntk = tok >> 3, ggk = tok & 7;
            const int ks2 = tok >> 3, kk2 = tok & 7;
            float ka[4] = {kv.x, kv.y, kv.z, kv.w};
            float va[4] = {vv.x, vv.y, vv.z, vv.w};
#pragma unroll
            for (int e = 0; e < 4; e++) {
                const int dh = d4 + e;
                const int ks = dh >> 3, kk = dh & 7;
                Ks[(ks * 32 + ggk * 4 + (kk & 3)) * 36
                   + (ntk >> 1) * 4 + (ntk & 1) * 2 + (kk >> 2)] = f2tf(ka[e]);
                const int ntv = dh >> 3, ggv = dh & 7;
                Vs[(ks2 * 32 + ggv * 4 + (kk2 & 3)) * 20
                   + (ntv >> 1) * 4 + (ntv & 1) * 2 + (kk2 >> 2)] = f2tf(va[e]);
            }
        }
        __syncthreads();

        // ---- S = Q K^T (warp tile 32x32) ----
        float sacc[2][4][4];
#pragma unroll
        for (int i = 0; i < 2; i++)
#pragma unroll
            for (int n = 0; n < 4; n++)
#pragma unroll
                for (int e = 0; e < 4; e++) sacc[i][n][e] = 0.f;
#pragma unroll
        for (int ks = 0; ks < 8; ks++) {
            uint4 afr[2], bfr[2];
#pragma unroll
            for (int i = 0; i < 2; i++)
                afr[i] = *(const uint4*)&Qs[(((2 * wm + i) * 8 + ks) * 32 + lane) * 4];
#pragma unroll
            for (int j = 0; j < 2; j++)
                bfr[j] = *(const uint4*)&Ks[(ks * 32 + lane) * 36 + 8 * wn + 4 * j];
#pragma unroll
            for (int i = 0; i < 2; i++)
#pragma unroll
                for (int n = 0; n < 4; n++) {
                    const unsigned* bp = (const unsigned*)&bfr[n >> 1];
                    const unsigned b0 = (n & 1) ? bp[2] : bp[0];
                    const unsigned b1 = (n & 1) ? bp[3] : bp[1];
                    mma8(sacc[i][n], (const unsigned*)&afr[i], b0, b1);
                }
        }

        // ---- exp epilogue: W store + Ps store (v2) + row sums ----
#pragma unroll
        for (int i = 0; i < 2; i++) {
            const int rl = 32 * wm + 16 * i + g;
#pragma unroll
            for (int n = 0; n < 4; n++) {
                const float p0 = ex2(sacc[i][n][0]);
                const float p1 = ex2(sacc[i][n][1]);
                const float p2 = ex2(sacc[i][n][2]);
                const float p3 = ex2(sacc[i][n][3]);
                lr[i][0] += p0 + p1;
                lr[i][1] += p2 + p3;
                const int cl = 32 * wn + 8 * n + 2 * tq;
                const size_t wr = ((size_t)bh * SEQ + q0 + rl) * SEQ + kt * 128 + cl;
                *(float2*)(W + wr) = make_float2(p0, p1);
                *(float2*)(W + wr + (size_t)8 * SEQ) = make_float2(p2, p3);
                // P into A-fragment order (v2 stores: pairs are adjacent)
                const int mtp = 2 * wm + i, ksp = 4 * wn + n;
                const int base = (mtp * 16 + ksp) * 128;
                const int cc = 2 * tq;
                const int ln = g * 4 + (cc & 3);
                const int sl = (cc >> 2) << 1;
                *(uint2*)&Ps[base + ln * 4 + sl] =
                    make_uint2(f2tf(p0), f2tf(p2));
                *(uint2*)&Ps[base + (ln + 1) * 4 + sl] =
                    make_uint2(f2tf(p1), f2tf(p3));
            }
        }
        __syncthreads();

        // ---- PV: warp tile 32(m) x 16(dh), k over 128 tokens ----
#pragma unroll
        for (int ks2 = 0; ks2 < 16; ks2++) {
            uint4 pa[2];
#pragma unroll
            for (int i = 0; i < 2; i++)
                pa[i] = *(const uint4*)&Ps[(((2 * wm + i) * 16 + ks2) * 128) + lane * 4];
            const uint4 vb = *(const uint4*)&Vs[(ks2 * 32 + lane) * 20 + 4 * wn];
            const unsigned* vp2 = (const unsigned*)&vb;
#pragma unroll
            for (int i = 0; i < 2; i++)
#pragma unroll
                for (int n = 0; n < 2; n++)
                    mma8(oacc[i][n], (const unsigned*)&pa[i],
                         vp2[2 * n], vp2[2 * n + 1]);
        }
        __syncthreads();
    }

    // ---- reduce row sums: quad shuffle, publish per-wn partials ----
#pragma unroll
    for (int i = 0; i < 2; i++) {
#pragma unroll
        for (int hf = 0; hf < 2; hf++) {
            float s = lr[i][hf];
            s += __shfl_xor_sync(0xffffffffu, s, 1);
            s += __shfl_xor_sync(0xffffffffu, s, 2);
            lr[i][hf] = s;
        }
        if (tq == 0) {
            const int rl = 32 * wm + 16 * i + g;
            ls[wn * 128 + rl]     = lr[i][0];
            ls[wn * 128 + rl + 8] = lr[i][1];
        }
    }
    __syncthreads();
    if (t < 128) {
        const float inv = 1.f / (ls[t] + ls[t + 128] + ls[t + 256] + ls[t + 384]);
        ls[t] = inv;
        g_li[(size_t)bh * SEQ + q0 + t] = inv;
    }
    __syncthreads();

    // ---- scale O by 1/l, write attended [token, d_model] ----
#pragma unroll
    for (int i = 0; i < 2; i++) {
        const int rloc = 32 * wm + 16 * i + g;
        const float inv0 = ls[rloc], inv1 = ls[rloc + 8];
        const int rl = q0 + rloc;
#pragma unroll
        for (int n = 0; n < 2; n++) {
            const int dh = 16 * wn + 8 * n + 2 * tq;
            const size_t a0 = ((size_t)(b * SEQ) + rl) * D_MODEL + h * DH + dh;
            *(float2*)(g_att + a0) =
                make_float2(oacc[i][n][0] * inv0, oacc[i][n][1] * inv0);
            *(float2*)(g_att + a0 + (size_t)8 * D_MODEL) =
                make_float2(oacc[i][n][2] * inv1, oacc[i][n][3] * inv1);
        }
    }
}

// =====================================================================
// rowwise normalize: W[row, :] *= inv_l[row]
// =====================================================================
__global__ __launch_bounds__(256)
void norm_w(float* __restrict__ W, const float* __restrict__ li)
{
    const size_t n4 = (size_t)BATCH * NHEAD * SEQ * SEQ / 4;
    const size_t stride = (size_t)gridDim.x * blockDim.x;
    for (size_t i = (size_t)blockIdx.x * blockDim.x + threadIdx.x; i < n4; i += stride) {
        float4 v = ((const float4*)W)[i];
        const float s = __ldg(&li[i >> 9]);   // 512 float4 per row
        v.x *= s; v.y *= s; v.z *= s; v.w *= s;
        ((float4*)W)[i] = v;
    }
}

// =====================================================================
// Launch
// =====================================================================
extern "C" void kernel_launch(void* const* d_in, const int* in_sizes, int n_in,
                              void* d_out, int out_size)
{
    (void)in_sizes; (void)n_in; (void)out_size;
    const float* x  = (const float*)d_in[0];
    const float* wq = (const float*)d_in[1];
    const float* bq = (const float*)d_in[2];
    const float* wk = (const float*)d_in[3];
    const float* bk = (const float*)d_in[4];
    const float* wv = (const float*)d_in[5];
    const float* bv = (const float*)d_in[6];
    const float* wo = (const float*)d_in[7];
    const float* bo = (const float*)d_in[8];

    float* out_p = (float*)d_out;                  // [4096, 1024]
    float* wts_p = (float*)d_out + OUT_ELEMS;      // [2,16,2048,2048]

    float *qp, *kp, *vp, *ap, *lip;
    cudaGetSymbolAddress((void**)&qp, g_q);
    cudaGetSymbolAddress((void**)&kp, g_k);
    cudaGetSymbolAddress((void**)&vp, g_v);
    cudaGetSymbolAddress((void**)&ap, g_att);
    cudaGetSymbolAddress((void**)&lip, g_li);

    cudaFuncSetAttribute(gemm_qkv, cudaFuncAttributeMaxDynamicSharedMemorySize, G_SMEM);
    cudaFuncSetAttribute(gemm_out, cudaFuncAttributeMaxDynamicSharedMemorySize, G_SMEM);
    cudaFuncSetAttribute(attn_tf32, cudaFuncAttributeMaxDynamicSharedMemorySize, ATTN_SMEM);

    gemm_qkv<<<dim3(D_MODEL / 128, TOK / 128, 3), 256, G_SMEM>>>(
        x, wq, wk, wv, bq, bk, bv, qp, kp, vp);

    attn_tf32<<<dim3(SEQ / 128, NHEAD, BATCH), 512, ATTN_SMEM>>>(wts_p);
    norm_w<<<8192, 256>>>(wts_p, lip);

    gemm_out<<<dim3(D_MODEL / 128, TOK / 128), 256, G_SMEM>>>(ap, wo, bo, out_p);
}